// round 16
// baseline (speedup 1.0000x reference)
#include <cuda_runtime.h>

#define Hh 720
#define Ww 1440
#define BW 10
#define RSTRIP 5           // output rows per strip (720 = 144 * 5)

__device__ __forceinline__ float4 f4add(const float4 a, const float4 b) {
    return make_float4(a.x + b.x, a.y + b.y, a.z + b.z, a.w + b.w);
}
__device__ __forceinline__ float4 f4sub(const float4 a, const float4 b) {
    return make_float4(a.x - b.x, a.y - b.y, a.z - b.z, a.w - b.w);
}
__device__ __forceinline__ float4 f4scale(const float4 a, const float s) {
    return make_float4(a.x * s, a.y * s, a.z * s, a.w * s);
}
__device__ __forceinline__ void stcs4(float* p, const float4 v) {
    asm volatile("st.global.cs.v4.f32 [%0], {%1,%2,%3,%4};"
                 :: "l"(p), "f"(v.x), "f"(v.y), "f"(v.z), "f"(v.w) : "memory");
}

// Guarded row load (zero-fill OOB rows): 8 floats, cols c0-2..c0+5.
__device__ __forceinline__ void loadrow8(const float* __restrict__ xp, int r, int cb,
                                         float2& L, float4& B, float2& R)
{
    if ((unsigned)r < (unsigned)Hh) {
        const float* p = xp + (size_t)r * Ww + cb;
        L = *reinterpret_cast<const float2*>(p + 2);
        B = *reinterpret_cast<const float4*>(p + 4);
        R = *reinterpret_cast<const float2*>(p + 8);
    } else {
        L = make_float2(0.f, 0.f);
        B = make_float4(0.f, 0.f, 0.f, 0.f);
        R = make_float2(0.f, 0.f);
    }
}

// Unguarded row load for strips whose full reach is in-bounds.
__device__ __forceinline__ void loadrow8u(const float* __restrict__ xp, int r, int cb,
                                          float2& L, float4& B, float2& R)
{
    const float* p = xp + (size_t)r * Ww + cb;
    L = *reinterpret_cast<const float2*>(p + 2);
    B = *reinterpret_cast<const float4*>(p + 4);
    R = *reinterpret_cast<const float2*>(p + 8);
}

__device__ __forceinline__ float4 hfrom8(const float2 L, const float4 B, const float2 R)
{
    float4 h;
    h.x = ((L.x + L.y) + (B.x + B.y)) + B.z;
    h.y = h.x - L.x + B.w;
    h.z = h.y - L.y + R.x;
    h.w = h.z - B.x + R.y;
    return h;
}

__global__ __launch_bounds__(128, 8)
void seg_smooth(const float* __restrict__ x, float* __restrict__ out)
{
    const int tid   = threadIdx.x;
    const int gi0   = blockIdx.y * RSTRIP;
    const int plane = blockIdx.z;
    const float* __restrict__ xp = x   + (size_t)plane * (Hh * Ww);
    float* __restrict__       op = out + (size_t)plane * (Hh * Ww);

    if (blockIdx.x < 3) {
        // ========= pure columns 12..1427: rolling ring, 2-row prefetch ======
        const int g = blockIdx.x * 128 + tid;
        if (g < 3 || g > 356) return;
        const int cb = 4 * g - 4;

        // Fast strips: mask-interior AND all loads (rows gi0-2 .. gi0+RSTRIP+3)
        // in-bounds.
        const bool fast = (gi0 >= BW + 2) && (gi0 + RSTRIP <= Hh - BW - 2) &&
                          (gi0 >= 2) && (gi0 + RSTRIP + 3 < Hh);

        float4 h[5];
        float2 Lp[2], Rp[2]; float4 Bp[2];
        float* os = op + (size_t)gi0 * Ww + (cb + 4);

        if (fast) {
            {
                float2 L, R; float4 B;
                loadrow8u(xp, gi0 - 2, cb, L, B, R); h[0] = hfrom8(L, B, R);
                loadrow8u(xp, gi0 - 1, cb, L, B, R); h[1] = hfrom8(L, B, R);
                loadrow8u(xp, gi0    , cb, L, B, R); h[2] = hfrom8(L, B, R);
                loadrow8u(xp, gi0 + 1, cb, L, B, R); h[3] = hfrom8(L, B, R);
            }
            float4 acc = f4add(f4add(h[0], h[1]), f4add(h[2], h[3]));
            loadrow8u(xp, gi0 + 2, cb, Lp[0], Bp[0], Rp[0]);
            loadrow8u(xp, gi0 + 3, cb, Lp[1], Bp[1], Rp[1]);

            #pragma unroll
            for (int b = 0; b < RSTRIP; ++b) {
                const int i = gi0 + b;
                const int s = b & 1;
                const float4 hn = hfrom8(Lp[s], Bp[s], Rp[s]);
                if (b < RSTRIP - 2)
                    loadrow8u(xp, i + 4, cb, Lp[s], Bp[s], Rp[s]);
                h[(b + 4) % 5] = hn;
                const float4 S = f4add(acc, hn);
                stcs4(os, f4scale(S, 0.04f));
                os += Ww;
                acc = f4sub(S, h[b]);
            }
        } else {
            {
                float2 L, R; float4 B;
                loadrow8(xp, gi0 - 2, cb, L, B, R); h[0] = hfrom8(L, B, R);
                loadrow8(xp, gi0 - 1, cb, L, B, R); h[1] = hfrom8(L, B, R);
                loadrow8(xp, gi0    , cb, L, B, R); h[2] = hfrom8(L, B, R);
                loadrow8(xp, gi0 + 1, cb, L, B, R); h[3] = hfrom8(L, B, R);
            }
            float4 acc = f4add(f4add(h[0], h[1]), f4add(h[2], h[3]));
            loadrow8(xp, gi0 + 2, cb, Lp[0], Bp[0], Rp[0]);
            loadrow8(xp, gi0 + 3, cb, Lp[1], Bp[1], Rp[1]);

            #pragma unroll
            for (int b = 0; b < RSTRIP; ++b) {
                const int i = gi0 + b;
                const int s = b & 1;
                const float4 hn = hfrom8(Lp[s], Bp[s], Rp[s]);
                if (b < RSTRIP - 2)
                    loadrow8(xp, i + 4, cb, Lp[s], Bp[s], Rp[s]);
                h[(b + 4) % 5] = hn;
                const float4 S = f4add(acc, hn);

                float4 o;
                if (i >= BW + 2 && i < Hh - BW - 2) {
                    o = f4scale(S, 0.04f);
                } else {
                    float4 NB = make_float4(0.f, 0.f, 0.f, 0.f);
                    #pragma unroll
                    for (int k = 0; k < 5; ++k) {
                        const int rk = i - 2 + k;            // OOB rows: h == 0
                        if (rk < BW || rk >= Hh - BW)
                            NB = f4add(NB, h[(b + k) % 5]);
                    }
                    const int r0 = max(i - 2, 0), r1 = min(i + 2, Hh - 1);
                    const int nrows = r1 - r0 + 1;
                    const int nbr = max(0, min(r1, BW - 1) - r0 + 1)
                                  + max(0, r1 - max(r0, Hh - BW) + 1);
                    if (i < BW || i >= Hh - BW)
                        o = f4scale(NB, 1.0f / (float)(5 * nbr));
                    else
                        o = f4scale(f4sub(S, NB),
                                    1.0f / (float)(5 * (nrows - nbr)));
                }
                stcs4(os, o);
                os += Ww;
                acc = f4sub(S, h[b]);
            }
        }
    } else {
        // ========== frame columns 0..11 and 1428..1439 (naive) ==========
        for (int idx = tid; idx < 6 * RSTRIP; idx += 128) {
            const int q  = idx % 6;
            const int i  = gi0 + idx / 6;
            const int gq = (q < 3) ? q : (q + 354);          // {0,1,2,357,358,359}
            const int cb = 4 * gq - 4;
            const bool Aok = (cb >= 0);
            const bool Cok = (cb + 11 < Ww);

            float m[8];
            #pragma unroll
            for (int c = 0; c < 8; ++c) {
                const int col = cb + 2 + c;
                m[c] = (col < BW || col >= Ww - BW) ? 1.0f : 0.0f;
            }

            float4 S  = make_float4(0.f, 0.f, 0.f, 0.f);
            float4 NB = make_float4(0.f, 0.f, 0.f, 0.f);
            #pragma unroll
            for (int k = 0; k < 5; ++k) {
                const int r = i - 2 + k;
                if ((unsigned)r < (unsigned)Hh) {
                    const float* rowp = xp + (size_t)r * Ww;
                    const float4 Af = Aok ? *(const float4*)(rowp + cb)
                                          : make_float4(0.f, 0.f, 0.f, 0.f);
                    const float4 Bf = *(const float4*)(rowp + cb + 4);
                    const float4 Cf = Cok ? *(const float4*)(rowp + cb + 8)
                                          : make_float4(0.f, 0.f, 0.f, 0.f);
                    float4 h;
                    h.x = ((Af.z + Af.w) + (Bf.x + Bf.y)) + Bf.z;
                    h.y = h.x - Af.z + Bf.w;
                    h.z = h.y - Af.w + Cf.x;
                    h.w = h.z - Bf.x + Cf.y;
                    S = f4add(S, h);
                    if (r < BW || r >= Hh - BW) {
                        NB = f4add(NB, h);
                    } else {
                        const float w0 = Af.z * m[0], w1 = Af.w * m[1];
                        const float w2 = Bf.x * m[2], w3 = Bf.y * m[3];
                        const float w4 = Bf.z * m[4], w5 = Bf.w * m[5];
                        const float w6 = Cf.x * m[6], w7 = Cf.y * m[7];
                        float4 hb;
                        hb.x = ((w0 + w1) + (w2 + w3)) + w4;
                        hb.y = hb.x - w0 + w5;
                        hb.z = hb.y - w1 + w6;
                        hb.w = hb.z - w2 + w7;
                        NB = f4add(NB, hb);
                    }
                }
            }
            const int r0 = max(i - 2, 0), r1 = min(i + 2, Hh - 1);
            const int nrows = r1 - r0 + 1;
            const int nbr = max(0, min(r1, BW - 1) - r0 + 1)
                          + max(0, r1 - max(r0, Hh - BW) + 1);
            const bool rowBi = (i < BW || i >= Hh - BW);
            const float sv[4]  = {S.x, S.y, S.z, S.w};
            const float nbv[4] = {NB.x, NB.y, NB.z, NB.w};
            float ov[4];
            #pragma unroll
            for (int c = 0; c < 4; ++c) {
                const int j  = cb + 4 + c;
                const int c0 = max(j - 2, 0), c1 = min(j + 2, Ww - 1);
                const int ncols = c1 - c0 + 1;
                const int nbc = max(0, min(c1, BW - 1) - c0 + 1)
                              + max(0, c1 - max(c0, Ww - BW) + 1);
                const int  cntB = nbr * ncols + (nrows - nbr) * nbc;
                const bool mb   = rowBi || (j < BW || j >= Ww - BW);
                const float num = mb ? nbv[c] : (sv[c] - nbv[c]);
                const int   cnt = mb ? cntB : (nrows * ncols - cntB);
                ov[c] = num / (float)cnt;
            }
            stcs4(op + (size_t)i * Ww + (cb + 4),
                  make_float4(ov[0], ov[1], ov[2], ov[3]));
        }
    }
}

extern "C" void kernel_launch(void* const* d_in, const int* in_sizes, int n_in,
                              void* d_out, int out_size)
{
    const float* x = (const float*)d_in[0];
    float* out = (float*)d_out;
    const int planes = out_size / (Hh * Ww);     // 64
    dim3 grid(4, Hh / RSTRIP, planes);           // 4 x 144 x 64 = 36864 blocks
    seg_smooth<<<grid, 128>>>(x, out);
}

// round 17
// speedup vs baseline: 1.0651x; 1.0651x over previous
#include <cuda_runtime.h>

#define Hh 720
#define Ww 1440
#define BW 10
#define RSTRIP 10          // output rows per strip (720 = 72 * 10)
#define FCOARSE 4          // frame blocks cover FCOARSE strips each

__device__ __forceinline__ float4 f4add(const float4 a, const float4 b) {
    return make_float4(a.x + b.x, a.y + b.y, a.z + b.z, a.w + b.w);
}
__device__ __forceinline__ float4 f4sub(const float4 a, const float4 b) {
    return make_float4(a.x - b.x, a.y - b.y, a.z - b.z, a.w - b.w);
}
__device__ __forceinline__ float4 f4scale(const float4 a, const float s) {
    return make_float4(a.x * s, a.y * s, a.z * s, a.w * s);
}
__device__ __forceinline__ void stcs4(float* p, const float4 v) {
    asm volatile("st.global.cs.v4.f32 [%0], {%1,%2,%3,%4};"
                 :: "l"(p), "f"(v.x), "f"(v.y), "f"(v.z), "f"(v.w) : "memory");
}

// Guarded row load (zero-fill OOB rows): 8 floats, cols c0-2..c0+5.
__device__ __forceinline__ void loadrow8(const float* __restrict__ xp, int r, int cb,
                                         float2& L, float4& B, float2& R)
{
    if ((unsigned)r < (unsigned)Hh) {
        const float* p = xp + (size_t)r * Ww + cb;
        L = *reinterpret_cast<const float2*>(p + 2);
        B = *reinterpret_cast<const float4*>(p + 4);
        R = *reinterpret_cast<const float2*>(p + 8);
    } else {
        L = make_float2(0.f, 0.f);
        B = make_float4(0.f, 0.f, 0.f, 0.f);
        R = make_float2(0.f, 0.f);
    }
}

// Unguarded row load for strips whose full reach is in-bounds.
__device__ __forceinline__ void loadrow8u(const float* __restrict__ xp, int r, int cb,
                                          float2& L, float4& B, float2& R)
{
    const float* p = xp + (size_t)r * Ww + cb;
    L = *reinterpret_cast<const float2*>(p + 2);
    B = *reinterpret_cast<const float4*>(p + 4);
    R = *reinterpret_cast<const float2*>(p + 8);
}

__device__ __forceinline__ float4 hfrom8(const float2 L, const float4 B, const float2 R)
{
    float4 h;
    h.x = ((L.x + L.y) + (B.x + B.y)) + B.z;
    h.y = h.x - L.x + B.w;
    h.z = h.y - L.y + R.x;
    h.w = h.z - B.x + R.y;
    return h;
}

__global__ __launch_bounds__(128, 8)
void seg_smooth(const float* __restrict__ x, float* __restrict__ out)
{
    const int tid   = threadIdx.x;
    const int gi0   = blockIdx.y * RSTRIP;
    const int plane = blockIdx.z;
    const float* __restrict__ xp = x   + (size_t)plane * (Hh * Ww);
    float* __restrict__       op = out + (size_t)plane * (Hh * Ww);

    if (blockIdx.x < 3) {
        // ========= pure columns 12..1427: rolling ring, 2-row prefetch ======
        const int g = blockIdx.x * 128 + tid;
        if (g < 3 || g > 356) return;
        const int cb = 4 * g - 4;

        // Fast strips: mask-interior AND all loads (rows gi0-2 .. gi0+RSTRIP+3)
        // in-bounds.
        const bool fast = (gi0 >= BW + 2) && (gi0 + RSTRIP <= Hh - BW - 2) &&
                          (gi0 >= 2) && (gi0 + RSTRIP + 3 < Hh);

        float4 h[5];
        float2 Lp[2], Rp[2]; float4 Bp[2];
        float* os = op + (size_t)gi0 * Ww + (cb + 4);

        if (fast) {
            {
                float2 L, R; float4 B;
                loadrow8u(xp, gi0 - 2, cb, L, B, R); h[0] = hfrom8(L, B, R);
                loadrow8u(xp, gi0 - 1, cb, L, B, R); h[1] = hfrom8(L, B, R);
                loadrow8u(xp, gi0    , cb, L, B, R); h[2] = hfrom8(L, B, R);
                loadrow8u(xp, gi0 + 1, cb, L, B, R); h[3] = hfrom8(L, B, R);
            }
            float4 acc = f4add(f4add(h[0], h[1]), f4add(h[2], h[3]));
            loadrow8u(xp, gi0 + 2, cb, Lp[0], Bp[0], Rp[0]);
            loadrow8u(xp, gi0 + 3, cb, Lp[1], Bp[1], Rp[1]);

            #pragma unroll
            for (int b = 0; b < 10; ++b) {
                const int i  = gi0 + b;
                const int s  = b & 1;
                const int rb = b % 5;
                const float4 hn = hfrom8(Lp[s], Bp[s], Rp[s]);
                loadrow8u(xp, i + 4, cb, Lp[s], Bp[s], Rp[s]);
                h[(rb + 4) % 5] = hn;
                const float4 S = f4add(acc, hn);
                stcs4(os, f4scale(S, 0.04f));
                os += Ww;
                acc = f4sub(S, h[rb]);
            }
        } else {
            {
                float2 L, R; float4 B;
                loadrow8(xp, gi0 - 2, cb, L, B, R); h[0] = hfrom8(L, B, R);
                loadrow8(xp, gi0 - 1, cb, L, B, R); h[1] = hfrom8(L, B, R);
                loadrow8(xp, gi0    , cb, L, B, R); h[2] = hfrom8(L, B, R);
                loadrow8(xp, gi0 + 1, cb, L, B, R); h[3] = hfrom8(L, B, R);
            }
            float4 acc = f4add(f4add(h[0], h[1]), f4add(h[2], h[3]));
            loadrow8(xp, gi0 + 2, cb, Lp[0], Bp[0], Rp[0]);
            loadrow8(xp, gi0 + 3, cb, Lp[1], Bp[1], Rp[1]);

            #pragma unroll
            for (int b = 0; b < 10; ++b) {
                const int i  = gi0 + b;
                const int s  = b & 1;
                const int rb = b % 5;
                const float4 hn = hfrom8(Lp[s], Bp[s], Rp[s]);
                loadrow8(xp, i + 4, cb, Lp[s], Bp[s], Rp[s]);
                h[(rb + 4) % 5] = hn;
                const float4 S = f4add(acc, hn);

                float4 o;
                if (i >= BW + 2 && i < Hh - BW - 2) {
                    o = f4scale(S, 0.04f);
                } else {
                    float4 NB = make_float4(0.f, 0.f, 0.f, 0.f);
                    #pragma unroll
                    for (int k = 0; k < 5; ++k) {
                        const int rk = i - 2 + k;            // OOB rows: h == 0
                        if (rk < BW || rk >= Hh - BW)
                            NB = f4add(NB, h[(rb + k) % 5]);
                    }
                    const int r0 = max(i - 2, 0), r1 = min(i + 2, Hh - 1);
                    const int nrows = r1 - r0 + 1;
                    const int nbr = max(0, min(r1, BW - 1) - r0 + 1)
                                  + max(0, r1 - max(r0, Hh - BW) + 1);
                    if (i < BW || i >= Hh - BW)
                        o = f4scale(NB, 1.0f / (float)(5 * nbr));
                    else
                        o = f4scale(f4sub(S, NB),
                                    1.0f / (float)(5 * (nrows - nbr)));
                }
                stcs4(os, o);
                os += Ww;
                acc = f4sub(S, h[rb]);
            }
        }
    } else {
        // ========== frame columns 0..11 and 1428..1439 (naive) ==========
        // Coarsened: only every FCOARSE-th y-block is active; it covers
        // FCOARSE strips (FCOARSE*RSTRIP rows). Inactive blocks exit at once.
        if (blockIdx.y % FCOARSE != 0) return;
        const int nitems = 6 * RSTRIP * FCOARSE;             // 240
        for (int idx = tid; idx < nitems; idx += 128) {
            const int q  = idx % 6;
            const int i  = gi0 + idx / 6;                    // gi0 .. gi0+39
            const int gq = (q < 3) ? q : (q + 354);          // {0,1,2,357,358,359}
            const int cb = 4 * gq - 4;
            const bool Aok = (cb >= 0);
            const bool Cok = (cb + 11 < Ww);

            float m[8];
            #pragma unroll
            for (int c = 0; c < 8; ++c) {
                const int col = cb + 2 + c;
                m[c] = (col < BW || col >= Ww - BW) ? 1.0f : 0.0f;
            }

            float4 S  = make_float4(0.f, 0.f, 0.f, 0.f);
            float4 NB = make_float4(0.f, 0.f, 0.f, 0.f);
            #pragma unroll
            for (int k = 0; k < 5; ++k) {
                const int r = i - 2 + k;
                if ((unsigned)r < (unsigned)Hh) {
                    const float* rowp = xp + (size_t)r * Ww;
                    const float4 Af = Aok ? *(const float4*)(rowp + cb)
                                          : make_float4(0.f, 0.f, 0.f, 0.f);
                    const float4 Bf = *(const float4*)(rowp + cb + 4);
                    const float4 Cf = Cok ? *(const float4*)(rowp + cb + 8)
                                          : make_float4(0.f, 0.f, 0.f, 0.f);
                    float4 h;
                    h.x = ((Af.z + Af.w) + (Bf.x + Bf.y)) + Bf.z;
                    h.y = h.x - Af.z + Bf.w;
                    h.z = h.y - Af.w + Cf.x;
                    h.w = h.z - Bf.x + Cf.y;
                    S = f4add(S, h);
                    if (r < BW || r >= Hh - BW) {
                        NB = f4add(NB, h);
                    } else {
                        const float w0 = Af.z * m[0], w1 = Af.w * m[1];
                        const float w2 = Bf.x * m[2], w3 = Bf.y * m[3];
                        const float w4 = Bf.z * m[4], w5 = Bf.w * m[5];
                        const float w6 = Cf.x * m[6], w7 = Cf.y * m[7];
                        float4 hb;
                        hb.x = ((w0 + w1) + (w2 + w3)) + w4;
                        hb.y = hb.x - w0 + w5;
                        hb.z = hb.y - w1 + w6;
                        hb.w = hb.z - w2 + w7;
                        NB = f4add(NB, hb);
                    }
                }
            }
            const int r0 = max(i - 2, 0), r1 = min(i + 2, Hh - 1);
            const int nrows = r1 - r0 + 1;
            const int nbr = max(0, min(r1, BW - 1) - r0 + 1)
                          + max(0, r1 - max(r0, Hh - BW) + 1);
            const bool rowBi = (i < BW || i >= Hh - BW);
            const float sv[4]  = {S.x, S.y, S.z, S.w};
            const float nbv[4] = {NB.x, NB.y, NB.z, NB.w};
            float ov[4];
            #pragma unroll
            for (int c = 0; c < 4; ++c) {
                const int j  = cb + 4 + c;
                const int c0 = max(j - 2, 0), c1 = min(j + 2, Ww - 1);
                const int ncols = c1 - c0 + 1;
                const int nbc = max(0, min(c1, BW - 1) - c0 + 1)
                              + max(0, c1 - max(c0, Ww - BW) + 1);
                const int  cntB = nbr * ncols + (nrows - nbr) * nbc;
                const bool mb   = rowBi || (j < BW || j >= Ww - BW);
                const float num = mb ? nbv[c] : (sv[c] - nbv[c]);
                const int   cnt = mb ? cntB : (nrows * ncols - cntB);
                ov[c] = num / (float)cnt;
            }
            stcs4(op + (size_t)i * Ww + (cb + 4),
                  make_float4(ov[0], ov[1], ov[2], ov[3]));
        }
    }
}

extern "C" void kernel_launch(void* const* d_in, const int* in_sizes, int n_in,
                              void* d_out, int out_size)
{
    const float* x = (const float*)d_in[0];
    float* out = (float*)d_out;
    const int planes = out_size / (Hh * Ww);     // 64
    dim3 grid(4, Hh / RSTRIP, planes);           // 4 x 72 x 64 = 18432 blocks
    seg_smooth<<<grid, 128>>>(x, out);
}